// round 15
// baseline (speedup 1.0000x reference)
#include <cuda_runtime.h>
#include <cuda_bf16.h>
#include <cstdint>

#define B_SZ 1024
#define E_SZ 512
#define C_SZ 16384

#define GRID_MAIN 296
#define NTILES    1024

// ---------------- scratch: chunk-major pre-swizzled tile images ----------------
__device__ __align__(16) char g_proxyQ[(size_t)C_SZ * E_SZ * 2];
__device__ __align__(16) char g_inputQ[(size_t)B_SZ * E_SZ * 2];
__device__ __align__(16) float g_outlier[C_SZ];
__device__ __align__(16) float g_invEff[C_SZ];
__device__ float g_Spos[C_SZ];
__device__ float g_Sneg[C_SZ];
__device__ float g_Nsum[C_SZ];

// zeroed each launch by cudaMemsetAsync (graph-capturable)
struct ZeroBlk {
    unsigned tileCtr;
    unsigned finCtr;
    float fin[4];
    int cTileCnt[128];   // target 17: 16 row-blocks + 1 const-block
    int inGrpCnt[8];     // target 16
};
__device__ ZeroBlk g_z;

// exp(32*(...)) via MUFU.EX2
__device__ __forceinline__ float ex2(float x) {
    float r;
    asm("ex2.approx.f32 %0, %1;" : "=f"(r) : "f"(x));
    return r;
}
#define A_L2E 46.166241308446828f   // 32 * log2(e)

__device__ __forceinline__ float flog1p(float x) {
    float r;
    asm("lg2.approx.f32 %0, %1;" : "=f"(r) : "f"(1.0f + x));
    return 0.693147180559945f * r;
}

// ---------------- HMMA / async helpers ----------------
__device__ __forceinline__ uint32_t smem_u32(const void* p) {
    uint32_t a;
    asm("{ .reg .u64 t; cvta.to.shared.u64 t, %1; cvt.u32.u64 %0, t; }" : "=r"(a) : "l"(p));
    return a;
}
__device__ __forceinline__ void mma16816(float* d, const uint32_t* a, const uint32_t* b) {
    asm volatile(
        "mma.sync.aligned.m16n8k16.row.col.f32.bf16.bf16.f32 "
        "{%0,%1,%2,%3}, {%4,%5,%6,%7}, {%8,%9}, {%0,%1,%2,%3};\n"
        : "+f"(d[0]), "+f"(d[1]), "+f"(d[2]), "+f"(d[3])
        : "r"(a[0]), "r"(a[1]), "r"(a[2]), "r"(a[3]), "r"(b[0]), "r"(b[1]));
}
#define LDSM_X4(r, a) \
    asm volatile("ldmatrix.sync.aligned.m8n8.x4.shared.b16 {%0,%1,%2,%3}, [%4];" \
        : "=r"((r)[0]), "=r"((r)[1]), "=r"((r)[2]), "=r"((r)[3]) : "r"(a))

__device__ __forceinline__ void bulkcp(uint32_t dst, const void* src, uint32_t bytes, uint32_t mbar) {
    asm volatile(
        "cp.async.bulk.shared::cluster.global.mbarrier::complete_tx::bytes [%0], [%1], %2, [%3];"
        :: "r"(dst), "l"(src), "r"(bytes), "r"(mbar) : "memory");
}
__device__ __forceinline__ void mbar_init(uint32_t mbar, uint32_t cnt) {
    asm volatile("mbarrier.init.shared.b64 [%0], %1;" :: "r"(mbar), "r"(cnt) : "memory");
}
__device__ __forceinline__ void mbar_expect(uint32_t mbar, uint32_t bytes) {
    asm volatile("mbarrier.arrive.expect_tx.shared.b64 _, [%0], %1;" :: "r"(mbar), "r"(bytes) : "memory");
}
__device__ __forceinline__ void mbar_wait(uint32_t mbar, uint32_t parity) {
    asm volatile(
        "{\n\t.reg .pred P;\n"
        "WL_%=:\n\t"
        "mbarrier.try_wait.parity.acquire.cta.shared::cta.b64 P, [%0], %1, 0x989680;\n\t"
        "@P bra.uni WD_%=;\n\t"
        "bra.uni WL_%=;\n"
        "WD_%=:\n\t}"
        :: "r"(mbar), "r"(parity) : "memory");
}
__device__ __forceinline__ int ldacq(const int* p) {
    int v;
    asm volatile("ld.global.acquire.gpu.b32 %0, [%1];" : "=r"(v) : "l"(p));
    return v;
}
__device__ __forceinline__ void waitTile(int t) {
    const int ct = t & 127, gp = t >> 7;
    while (ldacq(&g_z.cTileCnt[ct]) < 17) {}
    while (ldacq(&g_z.inGrpCnt[gp]) < 16) {}
}

// row r (128B rows), 16B granule g (0..7): xor swizzle
#define SWZ(r, g) ((r) * 128 + (((g) ^ ((r) & 7)) << 4))

// ---------------- fused persistent kernel: prep slice + HMMA mainloop ----------------
#define SM_TGT   0       // int [2][128]
#define SM_OUTL  1024    // float [2][128]
#define SM_IE    2048    // float [2][128]
#define SM_MBAR  3072    // 3 x 8B
#define SM_STG   4096    // 3 stages x (A 16KB + B 16KB)
#define SM_BYTES 102400

__global__ void __launch_bounds__(256, 2) mainFused(
    const float* __restrict__ inputs, const int* __restrict__ targets,
    const float* __restrict__ proxies, const float* __restrict__ effN,
    const float* __restrict__ ls)
{
    extern __shared__ __align__(1024) char sm[];
    __shared__ int sNext;
    const uint32_t smb = smem_u32(sm);
    const int tid = threadIdx.x;
    const int lane = tid & 31;
    const int warp = tid >> 5;
    const int warpM = warp >> 2;   // 0..1 (64 rows each)
    const int warpN = warp & 3;    // 0..3 (32 cols each)
    const int bid = blockIdx.x;

    if (tid == 0) {
        mbar_init(smb + SM_MBAR, 1);
        mbar_init(smb + SM_MBAR + 8, 1);
        mbar_init(smb + SM_MBAR + 16, 1);
    }
    __syncthreads();

    // ======== PHASE A: this CTA's prep slice (round-robin over 2240 blocks) ========
    // blocks 0..2047: proxy rows (normalize+bf16, swizzled image)
    // blocks 2048..2175: input rows (bf16, swizzled image)
    // blocks 2176..2239: per-class constants + accumulator zero
#pragma unroll 1
    for (int pb = bid; pb < 2240; pb += GRID_MAIN) {
        if (pb < 2176) {
            int row = pb * 8 + warp;
            bool isProxy = row < C_SZ;
            int drow = isProxy ? row : row - C_SZ;
            const float4* p4 = (const float4*)((isProxy ? proxies : inputs) + (size_t)drow * E_SZ);
            float4 v[4];
            float s = 0.0f;
#pragma unroll
            for (int j = 0; j < 4; j++) {
                v[j] = p4[lane + j * 32];
                s += v[j].x * v[j].x + v[j].y * v[j].y + v[j].z * v[j].z + v[j].w * v[j].w;
            }
            float rn = 1.0f;
            if (isProxy) {
#pragma unroll
                for (int o = 16; o > 0; o >>= 1) s += __shfl_xor_sync(0xffffffffu, s, o);
                rn = rsqrtf(s + 1e-12f);
            }
            int grp = drow >> 7, lr = drow & 127;
            char* base = (isProxy ? g_proxyQ : g_inputQ) + ((size_t)grp * 8) * 16384;
#pragma unroll
            for (int j = 0; j < 4; j++) {
                __nv_bfloat162 lo = __floats2bfloat162_rn(v[j].x * rn, v[j].y * rn);
                __nv_bfloat162 hi = __floats2bfloat162_rn(v[j].z * rn, v[j].w * rn);
                uint2 pk;
                pk.x = *(uint32_t*)&lo;
                pk.y = *(uint32_t*)&hi;
                int g4 = lane + j * 32;
                int kch = g4 >> 4;
                int q = (g4 & 15) >> 1;
                int sub = (g4 & 1) * 8;
                *(uint2*)(base + kch * 16384 + lr * 128 + (((q ^ (lr & 7)) << 4) | sub)) = pk;
            }
        } else {
            int c = (pb - 2176) * 256 + tid;
            float eff = effN[c], l = ls[c];
            float wb = 1.0f / (1.0f + log1pf(eff));
            float eta = (1.0f + (1.0f - l)) * wb + 0.1f;   // K=1, LAM=0.1
            g_outlier[c] = l - eta;
            g_invEff[c] = 1.0f / fmaxf(1.0f, eff);
            g_Spos[c] = 0.0f;
            g_Sneg[c] = 0.0f;
            g_Nsum[c] = 0.0f;
        }
        __syncthreads();
        if (tid == 0) {
            __threadfence();   // release: data writes before counter bump
            if (pb < 2048) {
                atomicAdd(&g_z.cTileCnt[pb >> 4], 1);
            } else if (pb < 2176) {
                atomicAdd(&g_z.inGrpCnt[(pb - 2048) >> 4], 1);
            } else {
                int idx = pb - 2176;
                atomicAdd(&g_z.cTileCnt[2 * idx], 1);
                atomicAdd(&g_z.cTileCnt[2 * idx + 1], 1);
            }
        }
    }

    // ======== PHASE B: persistent HMMA mainloop (dynamic tiles, bulk pipeline) ========
    float acc[4][4][4];
#pragma unroll
    for (int i = 0; i < 4; i++)
#pragma unroll
        for (int j = 0; j < 4; j++)
#pragma unroll
            for (int e = 0; e < 4; e++) acc[i][j][e] = 0.0f;

#define PREFETCH_T(tt_, k_, sidx_, par_) do { \
        if (tid == 0) { \
            uint32_t mb_ = smb + SM_MBAR + (sidx_) * 8; \
            uint32_t stg_ = smb + SM_STG + (sidx_) * 32768; \
            if ((k_) == 0) { \
                mbar_expect(mb_, 32768u + 1536u); \
                const int cB_ = ((tt_) & 127) << 7, mB_ = ((tt_) >> 7) << 7; \
                int pb_ = (par_) << 9; \
                bulkcp(smb + SM_TGT  + pb_, targets   + mB_, 512u, mb_); \
                bulkcp(smb + SM_OUTL + pb_, g_outlier + cB_, 512u, mb_); \
                bulkcp(smb + SM_IE   + pb_, g_invEff  + cB_, 512u, mb_); \
            } else { \
                mbar_expect(mb_, 32768u); \
            } \
            bulkcp(stg_,         g_inputQ + ((((size_t)(tt_) >> 7) * 8 + (k_)) << 14), 16384u, mb_); \
            bulkcp(stg_ + 16384, g_proxyQ + ((((size_t)(tt_) & 127) * 8 + (k_)) << 14), 16384u, mb_); \
        } \
    } while (0)

    int cur = bid;          // first tile: static seed
    int nxt = NTILES;       // sentinel until claimed
    int curPar = 0;
    int k = 0;
    int gm = 0, g3 = 0;

    if (tid == 0) waitTile(cur);
    PREFETCH_T(cur, 0, 0, 0);
    PREFETCH_T(cur, 1, 1, 0);

#pragma unroll 1
    while (true) {
        mbar_wait(smb + SM_MBAR + gm * 8, g3);
        __syncthreads();

        if (k == 4) nxt = sNext;

        {
            int pk = k + 2;
            int s2 = gm + 2; if (s2 >= 3) s2 -= 3;
            if (pk < 8) {
                PREFETCH_T(cur, pk, s2, curPar);
            } else if (nxt < NTILES) {
                if (tid == 0 && pk == 8) waitTile(nxt);
                PREFETCH_T(nxt, pk - 8, s2, curPar ^ 1);
            }
        }
        if (k == 3 && tid == 0) sNext = (int)(GRID_MAIN + atomicAdd(&g_z.tileCtr, 1u));

        const uint32_t aBase = smb + SM_STG + gm * 32768;
        const uint32_t bBase = aBase + 16384;
#pragma unroll
        for (int ks = 0; ks < 4; ks++) {
            uint32_t a[4][4], bfr[2][4];
#pragma unroll
            for (int mt = 0; mt < 4; mt++) {
                int r = warpM * 64 + mt * 16 + (lane & 15);
                int q = ks * 2 + (lane >> 4);
                LDSM_X4(a[mt], aBase + SWZ(r, q));
            }
#pragma unroll
            for (int np = 0; np < 2; np++) {
                int n = warpN * 32 + np * 16 + ((lane >> 4) << 3) + (lane & 7);
                int q = ks * 2 + ((lane >> 3) & 1);
                LDSM_X4(bfr[np], bBase + SWZ(n, q));
            }
#pragma unroll
            for (int mt = 0; mt < 4; mt++)
#pragma unroll
                for (int nt = 0; nt < 4; nt++)
                    mma16816(acc[mt][nt], a[mt], &bfr[nt >> 1][(nt & 1) * 2]);
        }

        if (k == 7) {
            const int cBase = (cur & 127) << 7;
            const int par = curPar << 7;
            const int* shTgt = (const int*)(sm + SM_TGT) + par;
            const float* shOutl = (const float*)(sm + SM_OUTL) + par;
            const float* shIE = (const float*)(sm + SM_IE) + par;

            int tg[4][2];
#pragma unroll
            for (int mt = 0; mt < 4; mt++) {
                int rl = warpM * 64 + mt * 16 + (lane >> 2);
                tg[mt][0] = shTgt[rl];
                tg[mt][1] = shTgt[rl + 8];
            }
#pragma unroll
            for (int nt = 0; nt < 4; nt++) {
#pragma unroll
                for (int p = 0; p < 2; p++) {
                    int cc = warpN * 32 + nt * 8 + (lane & 3) * 2 + p;
                    float outl = shOutl[cc];
                    float ie = shIE[cc];
                    float s1 = A_L2E * ie,  c1 = s1 * 0.1f;    // nv = ie
                    const float s0 = A_L2E, c0 = A_L2E * 0.1f; // nv = 1
                    int clsG = cBase + cc;
                    float sP = 0.0f, sN = 0.0f, sV = 0.0f;
#pragma unroll
                    for (int mt = 0; mt < 4; mt++) {
#pragma unroll
                        for (int h = 0; h < 2; h++) {
                            float cv = acc[mt][nt][h * 2 + p];
                            if (tg[mt][h] == clsG) {
                                sP += ex2(fmaf(-A_L2E, cv, c0));
                            } else {
                                bool low = (cv < outl);
                                sV += low ? ie : 1.0f;
                                float xr = low ? fmaf(s1, cv, c1) : fmaf(s0, cv, c0);
                                sN += ex2(xr);
                            }
                        }
                    }
#pragma unroll
                    for (int o = 4; o <= 16; o <<= 1) {
                        sP += __shfl_xor_sync(0xffffffffu, sP, o);
                        sN += __shfl_xor_sync(0xffffffffu, sN, o);
                        sV += __shfl_xor_sync(0xffffffffu, sV, o);
                    }
                    if ((lane >> 2) == 0) {
                        atomicAdd(&g_Spos[clsG], sP);
                        atomicAdd(&g_Sneg[clsG], sN);
                        atomicAdd(&g_Nsum[clsG], sV);
                    }
                }
            }
#pragma unroll
            for (int i = 0; i < 4; i++)
#pragma unroll
                for (int j = 0; j < 4; j++)
#pragma unroll
                    for (int e = 0; e < 4; e++) acc[i][j][e] = 0.0f;

            cur = nxt;
            curPar ^= 1;
            k = 0;
            if (++gm == 3) { gm = 0; g3 ^= 1; }
            if (cur >= NTILES) break;
        } else {
            k++;
            if (++gm == 3) { gm = 0; g3 ^= 1; }
        }
    }
}

// ---------------- finalize (16 blocks, smem histogram each, last block divides) ----------------
#define FIN_SMEM (C_SZ * 4 + 512)
__global__ void __launch_bounds__(1024) finalizeKernel(const int* __restrict__ targets,
                                                       float* __restrict__ out) {
    extern __shared__ int scnt[];
    float* wred = (float*)(scnt + C_SZ);
    const int tid = threadIdx.x;
    const int lane = tid & 31;
    const int warp = tid >> 5;

    for (int c = tid; c < C_SZ; c += 1024) scnt[c] = 0;
    __syncthreads();
    atomicAdd(&scnt[targets[tid]], 1);
    __syncthreads();

    int c = blockIdx.x * 1024 + tid;
    int cnt = scnt[c];
    float posT = 0.0f, posW = 0.0f;
    if (cnt > 0) { posW = 1.0f; posT = flog1p(g_Spos[c]); }
    float negT = flog1p(g_Sneg[c]);
    int Ncnt = B_SZ - cnt;
    float negW = (Ncnt > 0) ? g_Nsum[c] / (float)Ncnt : 0.0f;

#pragma unroll
    for (int o = 16; o > 0; o >>= 1) {
        posT += __shfl_xor_sync(0xffffffffu, posT, o);
        negT += __shfl_xor_sync(0xffffffffu, negT, o);
        posW += __shfl_xor_sync(0xffffffffu, posW, o);
        negW += __shfl_xor_sync(0xffffffffu, negW, o);
    }
    if (lane == 0) {
        wred[warp] = posT; wred[32 + warp] = negT;
        wred[64 + warp] = posW; wred[96 + warp] = negW;
    }
    __syncthreads();
    if (warp == 0) {
        float a0 = wred[lane], a1 = wred[32 + lane], a2 = wred[64 + lane], a3 = wred[96 + lane];
#pragma unroll
        for (int o = 16; o > 0; o >>= 1) {
            a0 += __shfl_xor_sync(0xffffffffu, a0, o);
            a1 += __shfl_xor_sync(0xffffffffu, a1, o);
            a2 += __shfl_xor_sync(0xffffffffu, a2, o);
            a3 += __shfl_xor_sync(0xffffffffu, a3, o);
        }
        if (lane == 0) {
            atomicAdd(&g_z.fin[0], a0);
            atomicAdd(&g_z.fin[1], a1);
            atomicAdd(&g_z.fin[2], a2);
            atomicAdd(&g_z.fin[3], a3);
            __threadfence();
            unsigned old = atomicAdd(&g_z.finCtr, 1u);
            if (old == gridDim.x - 1) {
                float f0 = atomicAdd(&g_z.fin[0], 0.0f);
                float f1 = atomicAdd(&g_z.fin[1], 0.0f);
                float f2 = atomicAdd(&g_z.fin[2], 0.0f);
                float f3 = atomicAdd(&g_z.fin[3], 0.0f);
                out[0] = f0 / f2 + f1 / f3;
            }
        }
    }
}

// ---------------- launch ----------------
extern "C" void kernel_launch(void* const* d_in, const int* in_sizes, int n_in,
                              void* d_out, int out_size) {
    const float* inputs  = (const float*)d_in[0];   // [B,E] f32
    const int*   targets = (const int*)d_in[1];     // [B]   i32
    const float* proxies = (const float*)d_in[2];   // [C,E] f32
    const float* effN    = (const float*)d_in[3];   // [C]
    const float* ls      = (const float*)d_in[4];   // [C]
    float* out = (float*)d_out;

    cudaFuncSetAttribute(mainFused, cudaFuncAttributeMaxDynamicSharedMemorySize, SM_BYTES);
    cudaFuncSetAttribute(finalizeKernel, cudaFuncAttributeMaxDynamicSharedMemorySize, FIN_SMEM);

    void* zp = nullptr;
    cudaGetSymbolAddress(&zp, g_z);
    cudaMemsetAsync(zp, 0, sizeof(ZeroBlk));

    mainFused<<<GRID_MAIN, 256, SM_BYTES>>>(inputs, targets, proxies, effN, ls);
    finalizeKernel<<<16, 1024, FIN_SMEM>>>(targets, out);
}

// round 16
// speedup vs baseline: 1.1005x; 1.1005x over previous
#include <cuda_runtime.h>
#include <cuda_bf16.h>
#include <cstdint>

#define B_SZ 1024
#define E_SZ 512
#define C_SZ 16384

#define GRID_MAIN 296
#define NTILES    1024

// ---------------- scratch: chunk-major pre-swizzled tile images ----------------
// g_proxyQ: [128 cTiles][8 chunks][16384B]  (exact smem image, SW-xor applied)
// g_inputQ: [8 mGroups][8 chunks][16384B]
__device__ __align__(16) char g_proxyQ[(size_t)C_SZ * E_SZ * 2];
__device__ __align__(16) char g_inputQ[(size_t)B_SZ * E_SZ * 2];
__device__ __align__(16) float g_outlier[C_SZ];
__device__ __align__(16) float g_invEff[C_SZ];
__device__ float g_Spos[C_SZ];
__device__ float g_Sneg[C_SZ];
__device__ float g_Nsum[C_SZ];
__device__ unsigned g_tileCtr;
__device__ float g_fin[4];
__device__ unsigned g_finCtr;

// exp(32*(...)) via MUFU.EX2
__device__ __forceinline__ float ex2(float x) {
    float r;
    asm("ex2.approx.f32 %0, %1;" : "=f"(r) : "f"(x));
    return r;
}
#define A_L2E 46.166241308446828f   // 32 * log2(e)

__device__ __forceinline__ float flog1p(float x) {
    float r;
    asm("lg2.approx.f32 %0, %1;" : "=f"(r) : "f"(1.0f + x));
    return 0.693147180559945f * r;
}

// ---------------- fused prep kernel ----------------
// blocks 0..2175  : row normalize + bf16, write chunk-major swizzled image
//                   rows 0..16383 proxies (L2-normalized), 16384..17407 inputs (copy)
// blocks 2176..2239: per-class constants + accumulator zero
__global__ void __launch_bounds__(256) prepKernel(
    const float* __restrict__ inputs,
    const float* __restrict__ proxies, const float* __restrict__ effN,
    const float* __restrict__ ls)
{
    const int b = blockIdx.x;
    const int tid = threadIdx.x;
    if (b < 2176) {
        int row = b * 8 + (tid >> 5);
        int lane = tid & 31;
        bool isProxy = row < C_SZ;
        int drow = isProxy ? row : row - C_SZ;
        const float4* p4 = (const float4*)((isProxy ? proxies : inputs) + (size_t)drow * E_SZ);
        float4 v[4];
        float s = 0.0f;
#pragma unroll
        for (int j = 0; j < 4; j++) {
            v[j] = p4[lane + j * 32];
            s += v[j].x * v[j].x + v[j].y * v[j].y + v[j].z * v[j].z + v[j].w * v[j].w;
        }
        float rn = 1.0f;
        if (isProxy) {
#pragma unroll
            for (int o = 16; o > 0; o >>= 1) s += __shfl_xor_sync(0xffffffffu, s, o);
            rn = rsqrtf(s + 1e-12f);
        }
        int grp = drow >> 7, lr = drow & 127;
        char* base = (isProxy ? g_proxyQ : g_inputQ) + ((size_t)grp * 8) * 16384;
#pragma unroll
        for (int j = 0; j < 4; j++) {
            __nv_bfloat162 lo = __floats2bfloat162_rn(v[j].x * rn, v[j].y * rn);
            __nv_bfloat162 hi = __floats2bfloat162_rn(v[j].z * rn, v[j].w * rn);
            uint2 pk;
            pk.x = *(uint32_t*)&lo;
            pk.y = *(uint32_t*)&hi;
            int g4 = lane + j * 32;          // float4 granule 0..127
            int kch = g4 >> 4;               // chunk (64 cols each)
            int q = (g4 & 15) >> 1;          // 16B granule within 128B chunk-row
            int sub = (g4 & 1) * 8;
            *(uint2*)(base + kch * 16384 + lr * 128 + (((q ^ (lr & 7)) << 4) | sub)) = pk;
        }
    } else {
        int c = (b - 2176) * 256 + tid;
        float eff = effN[c], l = ls[c];
        float wb = 1.0f / (1.0f + log1pf(eff));
        float eta = (1.0f + (1.0f - l)) * wb + 0.1f;   // K=1, LAM=0.1
        g_outlier[c] = l - eta;
        g_invEff[c] = 1.0f / fmaxf(1.0f, eff);
        g_Spos[c] = 0.0f;
        g_Sneg[c] = 0.0f;
        g_Nsum[c] = 0.0f;
        if (b == 2176 && tid == 0) {
            g_tileCtr = GRID_MAIN;
            g_finCtr = 0u;
            g_fin[0] = 0.0f; g_fin[1] = 0.0f; g_fin[2] = 0.0f; g_fin[3] = 0.0f;
        }
    }
}

// ---------------- HMMA / async helpers ----------------
__device__ __forceinline__ uint32_t smem_u32(const void* p) {
    uint32_t a;
    asm("{ .reg .u64 t; cvta.to.shared.u64 t, %1; cvt.u32.u64 %0, t; }" : "=r"(a) : "l"(p));
    return a;
}
__device__ __forceinline__ void mma16816(float* d, const uint32_t* a, const uint32_t* b) {
    asm volatile(
        "mma.sync.aligned.m16n8k16.row.col.f32.bf16.bf16.f32 "
        "{%0,%1,%2,%3}, {%4,%5,%6,%7}, {%8,%9}, {%0,%1,%2,%3};\n"
        : "+f"(d[0]), "+f"(d[1]), "+f"(d[2]), "+f"(d[3])
        : "r"(a[0]), "r"(a[1]), "r"(a[2]), "r"(a[3]), "r"(b[0]), "r"(b[1]));
}
#define LDSM_X4(r, a) \
    asm volatile("ldmatrix.sync.aligned.m8n8.x4.shared.b16 {%0,%1,%2,%3}, [%4];" \
        : "=r"((r)[0]), "=r"((r)[1]), "=r"((r)[2]), "=r"((r)[3]) : "r"(a))

__device__ __forceinline__ void cpa16(uint32_t s, const void* g) {
    asm volatile("cp.async.cg.shared.global [%0], [%1], 16;" :: "r"(s), "l"(g));
}
#define CP_COMMIT() asm volatile("cp.async.commit_group;" ::: "memory")

__device__ __forceinline__ void bulkcp(uint32_t dst, const void* src, uint32_t bytes, uint32_t mbar) {
    asm volatile(
        "cp.async.bulk.shared::cluster.global.mbarrier::complete_tx::bytes [%0], [%1], %2, [%3];"
        :: "r"(dst), "l"(src), "r"(bytes), "r"(mbar) : "memory");
}
__device__ __forceinline__ void mbar_init(uint32_t mbar, uint32_t cnt) {
    asm volatile("mbarrier.init.shared.b64 [%0], %1;" :: "r"(mbar), "r"(cnt) : "memory");
}
__device__ __forceinline__ void mbar_expect(uint32_t mbar, uint32_t bytes) {
    asm volatile("mbarrier.arrive.expect_tx.shared.b64 _, [%0], %1;" :: "r"(mbar), "r"(bytes) : "memory");
}
__device__ __forceinline__ void mbar_wait(uint32_t mbar, uint32_t parity) {
    asm volatile(
        "{\n\t.reg .pred P;\n"
        "WL_%=:\n\t"
        "mbarrier.try_wait.parity.acquire.cta.shared::cta.b64 P, [%0], %1, 0x989680;\n\t"
        "@P bra.uni WD_%=;\n\t"
        "bra.uni WL_%=;\n"
        "WD_%=:\n\t}"
        :: "r"(mbar), "r"(parity) : "memory");
}

// row r (128B rows), 16B granule g (0..7): xor swizzle
#define SWZ(r, g) ((r) * 128 + (((g) ^ ((r) & 7)) << 4))

// ---------------- persistent main HMMA kernel (bulk-copy pipeline) ----------------
#define SM_TGT   0       // int [2][128]
#define SM_OUTL  1024    // float [2][128]
#define SM_IE    2048    // float [2][128]
#define SM_MBAR  3072    // 3 x 8B
#define SM_STG   4096    // 3 stages x (A 16KB + B 16KB)
#define SM_BYTES 102400

__global__ void __launch_bounds__(256, 2) mainHMMA(const int* __restrict__ targets) {
    extern __shared__ __align__(1024) char sm[];
    __shared__ int sNext;
    const uint32_t smb = smem_u32(sm);
    const int tid = threadIdx.x;
    const int lane = tid & 31;
    const int warp = tid >> 5;
    const int warpM = warp >> 2;   // 0..1 (64 rows each)
    const int warpN = warp & 3;    // 0..3 (32 cols each)

    if (tid == 0) {
        mbar_init(smb + SM_MBAR, 1);
        mbar_init(smb + SM_MBAR + 8, 1);
        mbar_init(smb + SM_MBAR + 16, 1);
    }
    __syncthreads();

    float acc[4][4][4];
#pragma unroll
    for (int i = 0; i < 4; i++)
#pragma unroll
        for (int j = 0; j < 4; j++)
#pragma unroll
            for (int e = 0; e < 4; e++) acc[i][j][e] = 0.0f;

#define PREFETCH_T(tt_, k_, sidx_, par_) do { \
        if (tid == 0) { \
            uint32_t mb_ = smb + SM_MBAR + (sidx_) * 8; \
            uint32_t stg_ = smb + SM_STG + (sidx_) * 32768; \
            mbar_expect(mb_, 32768u); \
            bulkcp(stg_,         g_inputQ + ((((size_t)(tt_) >> 7) * 8 + (k_)) << 14), 16384u, mb_); \
            bulkcp(stg_ + 16384, g_proxyQ + ((((size_t)(tt_) & 127) * 8 + (k_)) << 14), 16384u, mb_); \
        } \
        if ((k_) == 0) { \
            const int cB_ = ((tt_) & 127) << 7, mB_ = ((tt_) >> 7) << 7; \
            int pb_ = (par_) << 9; \
            if (tid < 32)       cpa16(smb + SM_TGT  + pb_ + tid * 16,        targets   + mB_ + tid * 4); \
            else if (tid < 64)  cpa16(smb + SM_OUTL + pb_ + (tid - 32) * 16, g_outlier + cB_ + (tid - 32) * 4); \
            else if (tid < 96)  cpa16(smb + SM_IE   + pb_ + (tid - 64) * 16, g_invEff  + cB_ + (tid - 64) * 4); \
            CP_COMMIT(); \
        } \
    } while (0)

    int cur = blockIdx.x;   // first tile: static seed
    int nxt = NTILES;       // sentinel until claimed
    int curPar = 0;
    int k = 0;              // chunk within current tile
    int gm = 0, g3 = 0;     // stage index and phase parity

    PREFETCH_T(cur, 0, 0, 0);
    PREFETCH_T(cur, 1, 1, 0);

#pragma unroll 1
    while (true) {
        mbar_wait(smb + SM_MBAR + gm * 8, g3);
        __syncthreads();   // all warps done with the stage the next prefetch overwrites

        if (k == 4) nxt = sNext;

        {
            int pk = k + 2;
            int s2 = gm + 2; if (s2 >= 3) s2 -= 3;
            if (pk < 8)               PREFETCH_T(cur, pk, s2, curPar);
            else if (nxt < NTILES)    PREFETCH_T(nxt, pk - 8, s2, curPar ^ 1);
        }
        if (k == 3 && tid == 0) sNext = atomicAdd(&g_tileCtr, 1u);

        const uint32_t aBase = smb + SM_STG + gm * 32768;
        const uint32_t bBase = aBase + 16384;
#pragma unroll
        for (int ks = 0; ks < 4; ks++) {
            uint32_t a[4][4], bfr[2][4];
#pragma unroll
            for (int mt = 0; mt < 4; mt++) {
                int r = warpM * 64 + mt * 16 + (lane & 15);
                int q = ks * 2 + (lane >> 4);
                LDSM_X4(a[mt], aBase + SWZ(r, q));
            }
#pragma unroll
            for (int np = 0; np < 2; np++) {
                int n = warpN * 32 + np * 16 + ((lane >> 4) << 3) + (lane & 7);
                int q = ks * 2 + ((lane >> 3) & 1);
                LDSM_X4(bfr[np], bBase + SWZ(n, q));
            }
#pragma unroll
            for (int mt = 0; mt < 4; mt++)
#pragma unroll
                for (int nt = 0; nt < 4; nt++)
                    mma16816(acc[mt][nt], a[mt], &bfr[nt >> 1][(nt & 1) * 2]);
        }

        if (k == 7) {
            // constants were cp.async'd at this tile's k==0 (≥7 chunks ago)
            asm volatile("cp.async.wait_group 0;" ::: "memory");
            __syncthreads();

            const int cBase = (cur & 127) << 7;
            const int par = curPar << 7;
            const int* shTgt = (const int*)(sm + SM_TGT) + par;
            const float* shOutl = (const float*)(sm + SM_OUTL) + par;
            const float* shIE = (const float*)(sm + SM_IE) + par;

            int tg[4][2];
#pragma unroll
            for (int mt = 0; mt < 4; mt++) {
                int rl = warpM * 64 + mt * 16 + (lane >> 2);
                tg[mt][0] = shTgt[rl];
                tg[mt][1] = shTgt[rl + 8];
            }
#pragma unroll
            for (int nt = 0; nt < 4; nt++) {
#pragma unroll
                for (int p = 0; p < 2; p++) {
                    int cc = warpN * 32 + nt * 8 + (lane & 3) * 2 + p;
                    float outl = shOutl[cc];
                    float ie = shIE[cc];
                    float s1 = A_L2E * ie,  c1 = s1 * 0.1f;    // nv = ie
                    const float s0 = A_L2E, c0 = A_L2E * 0.1f; // nv = 1
                    int clsG = cBase + cc;
                    float sP = 0.0f, sN = 0.0f, sV = 0.0f;
#pragma unroll
                    for (int mt = 0; mt < 4; mt++) {
#pragma unroll
                        for (int h = 0; h < 2; h++) {
                            float cv = acc[mt][nt][h * 2 + p];
                            if (tg[mt][h] == clsG) {
                                sP += ex2(fmaf(-A_L2E, cv, c0));
                            } else {
                                bool low = (cv < outl);
                                sV += low ? ie : 1.0f;
                                float xr = low ? fmaf(s1, cv, c1) : fmaf(s0, cv, c0);
                                sN += ex2(xr);
                            }
                        }
                    }
#pragma unroll
                    for (int o = 4; o <= 16; o <<= 1) {
                        sP += __shfl_xor_sync(0xffffffffu, sP, o);
                        sN += __shfl_xor_sync(0xffffffffu, sN, o);
                        sV += __shfl_xor_sync(0xffffffffu, sV, o);
                    }
                    if ((lane >> 2) == 0) {
                        atomicAdd(&g_Spos[clsG], sP);
                        atomicAdd(&g_Sneg[clsG], sN);
                        atomicAdd(&g_Nsum[clsG], sV);
                    }
                }
            }
#pragma unroll
            for (int i = 0; i < 4; i++)
#pragma unroll
                for (int j = 0; j < 4; j++)
#pragma unroll
                    for (int e = 0; e < 4; e++) acc[i][j][e] = 0.0f;

            cur = nxt;
            curPar ^= 1;
            k = 0;
            if (++gm == 3) { gm = 0; g3 ^= 1; }
            if (cur >= NTILES) break;
        } else {
            k++;
            if (++gm == 3) { gm = 0; g3 ^= 1; }
        }
    }
}

// ---------------- finalize: 64 blocks x 256 threads, range-filtered histogram ----------------
__global__ void __launch_bounds__(256) finalizeKernel(const int* __restrict__ targets,
                                                      float* __restrict__ out) {
    __shared__ int hist[256];
    __shared__ float wred[4][8];
    const int tid = threadIdx.x;
    const int lane = tid & 31;
    const int warp = tid >> 5;
    const int cbase = blockIdx.x * 256;

    hist[tid] = 0;
    __syncthreads();
#pragma unroll
    for (int j = 0; j < 4; j++) {
        int t = targets[tid + j * 256];
        int loc = t - cbase;
        if ((unsigned)loc < 256u) atomicAdd(&hist[loc], 1);
    }
    __syncthreads();

    int c = cbase + tid;
    int cnt = hist[tid];
    float posT = 0.0f, posW = 0.0f;
    if (cnt > 0) { posW = 1.0f; posT = flog1p(g_Spos[c]); }
    float negT = flog1p(g_Sneg[c]);
    int Ncnt = B_SZ - cnt;
    float negW = (Ncnt > 0) ? g_Nsum[c] / (float)Ncnt : 0.0f;

#pragma unroll
    for (int o = 16; o > 0; o >>= 1) {
        posT += __shfl_xor_sync(0xffffffffu, posT, o);
        negT += __shfl_xor_sync(0xffffffffu, negT, o);
        posW += __shfl_xor_sync(0xffffffffu, posW, o);
        negW += __shfl_xor_sync(0xffffffffu, negW, o);
    }
    if (lane == 0) {
        wred[0][warp] = posT; wred[1][warp] = negT;
        wred[2][warp] = posW; wred[3][warp] = negW;
    }
    __syncthreads();
    if (tid == 0) {
        float a0 = 0.0f, a1 = 0.0f, a2 = 0.0f, a3 = 0.0f;
#pragma unroll
        for (int w = 0; w < 8; w++) {
            a0 += wred[0][w]; a1 += wred[1][w]; a2 += wred[2][w]; a3 += wred[3][w];
        }
        atomicAdd(&g_fin[0], a0);
        atomicAdd(&g_fin[1], a1);
        atomicAdd(&g_fin[2], a2);
        atomicAdd(&g_fin[3], a3);
        __threadfence();
        unsigned old = atomicAdd(&g_finCtr, 1u);
        if (old == gridDim.x - 1) {
            float f0 = atomicAdd(&g_fin[0], 0.0f);
            float f1 = atomicAdd(&g_fin[1], 0.0f);
            float f2 = atomicAdd(&g_fin[2], 0.0f);
            float f3 = atomicAdd(&g_fin[3], 0.0f);
            out[0] = f0 / f2 + f1 / f3;
        }
    }
}

// ---------------- launch ----------------
extern "C" void kernel_launch(void* const* d_in, const int* in_sizes, int n_in,
                              void* d_out, int out_size) {
    const float* inputs  = (const float*)d_in[0];   // [B,E] f32
    const int*   targets = (const int*)d_in[1];     // [B]   i32
    const float* proxies = (const float*)d_in[2];   // [C,E] f32
    const float* effN    = (const float*)d_in[3];   // [C]
    const float* ls      = (const float*)d_in[4];   // [C]
    float* out = (float*)d_out;

    cudaFuncSetAttribute(mainHMMA, cudaFuncAttributeMaxDynamicSharedMemorySize, SM_BYTES);

    prepKernel<<<2240, 256>>>(inputs, proxies, effN, ls);
    mainHMMA<<<GRID_MAIN, 256, SM_BYTES>>>(targets);
    finalizeKernel<<<64, 256>>>(targets, out);
}